// round 14
// baseline (speedup 1.0000x reference)
#include <cuda_runtime.h>
#include <cuda_fp16.h>
#include <stdint.h>

// LegoConv2d GB300 — R13: R12 skeleton + epilogue surgery.
// fp16 1-term mma.sync GEMM per slab (b,h): feat[256 x 64] = X^T @ lego,
// fp32 accum, permuted K (k = chunk*48 + tap*16 + c16), 2 CTAs/SM.
// NEW: transposed pre-multiplied gather tables (int4/float4 per o) and a
// vectorized float4 epilogue (7 iters, 2+4 LDS.128 + 16 FMA + 4 STG).

#define NCTA   304
#define NSLABS 608
#define FT_S   260            // feat row stride (f32), conflict-free dump

// smem byte offsets (per CTA, 100352 B total -> 2 CTAs/SM)
#define SM_XB0 0              // X buf0: 256 rows x 56 fp16 (stride 112B) = 28672
#define SM_XB1 28672
#define SM_LG  66560          // lego: 64 n x 200 fp16 (stride 400B) = 25600
#define SM_OFS 92160          // int4[256]  : idx[i,o]*FT_S + i*64
#define SM_CF4 96256          // float4[256]: coef[i,o]
#define SM_SZ  100352
// feat (f32 64 x FT_S = 66560 B) overlays both X buffers [0, 66560)

__device__ __forceinline__ uint32_t smem_u32(const void* p) {
    uint32_t a;
    asm("{ .reg .u64 t; cvta.to.shared.u64 t, %1; cvt.u32.u64 %0, t; }" : "=r"(a) : "l"(p));
    return a;
}
__device__ __forceinline__ void ldmx4(uint32_t* r, uint32_t addr) {
    asm volatile("ldmatrix.sync.aligned.m8n8.x4.shared.b16 {%0,%1,%2,%3}, [%4];"
                 : "=r"(r[0]), "=r"(r[1]), "=r"(r[2]), "=r"(r[3]) : "r"(addr));
}
__device__ __forceinline__ void mma_fp16(float* d, const uint32_t* a,
                                         uint32_t b0, uint32_t b1) {
    asm volatile(
        "mma.sync.aligned.m16n8k16.row.col.f32.f16.f16.f32 "
        "{%0,%1,%2,%3}, {%4,%5,%6,%7}, {%8,%9}, {%0,%1,%2,%3};"
        : "+f"(d[0]), "+f"(d[1]), "+f"(d[2]), "+f"(d[3])
        : "r"(a[0]), "r"(a[1]), "r"(a[2]), "r"(a[3]), "r"(b0), "r"(b1));
}
__device__ __forceinline__ uint32_t pkh2(float lo, float hi) {
    __half2 h = __floats2half2_rn(lo, hi);
    return *(uint32_t*)&h;
}

extern __shared__ char smem[];

__global__ __launch_bounds__(512, 2)
void main_kernel(const float* __restrict__ x,
                 const float* __restrict__ lego,
                 const float* __restrict__ coefs,
                 const float* __restrict__ comb,
                 float* __restrict__ out)
{
    const int t = threadIdx.x, lane = t & 31, wid = t >> 5;
    const uint32_t sb = smem_u32(smem);

    int*   ofs_s = (int*)(smem + SM_OFS);     // [o*4 + i]
    float* cf_s  = (float*)(smem + SM_CF4);   // [o*4 + i]

    // ---- fused prep: warp-parallel first-max argmax; write transposed,
    //      pre-multiplied tables: ofs = idx*FT_S + i*64, cf = coefficient
    for (int row = wid * 64; row < wid * 64 + 64; row++) {
        float v = comb[(size_t)row * 64 + lane];
        int   i = lane;
        {
            float v2 = comb[(size_t)row * 64 + 32 + lane];
            if (v2 > v) { v = v2; i = lane + 32; }
        }
        #pragma unroll
        for (int off = 16; off; off >>= 1) {
            float ov = __shfl_xor_sync(0xFFFFFFFFu, v, off);
            int   oi = __shfl_xor_sync(0xFFFFFFFFu, i, off);
            if (ov > v || (ov == v && oi < i)) { v = ov; i = oi; }
        }
        if (lane == 0) {
            const int o = row & 255, sp = row >> 8;      // row = sp*256 + o
            ofs_s[o * 4 + sp] = i * FT_S + sp * 64;
            cf_s[o * 4 + sp]  = coefs[(size_t)row * 64 + i];
        }
    }

    // ---- stage lego fp16 once, K-permuted: k = (c>>4)*48 + tap*16 + (c&15)
    {
        __half* lg = (__half*)(smem + SM_LG);
        for (int s = t; s < 64 * 192; s += 512) {
            int n = s / 192, r = s - n * 192, c = r / 3, tap = r - c * 3;
            int k = (c >> 4) * 48 + tap * 16 + (c & 15);
            lg[n * 200 + k] = __float2half_rn(lego[s]);
        }
    }
    __syncthreads();

    const int wm = wid & 3, wn = wid >> 2;      // warp grid 4(M) x 4(N)
    const int r  = lane >> 2, cq = lane & 3;

    // ldmatrix lane base addresses
    const uint32_t a_base = sb +
        (uint32_t)((wm * 64 + (lane & 15)) * 112 + (lane >> 4) * 16);
    const uint32_t b_base = sb + SM_LG +
        (uint32_t)((wn * 16 + 8 * ((lane >> 4) & 1) + (lane & 7)) * 400 +
                   16 * ((lane >> 3) & 1));

    float* feat = (float*)smem;

    // staging role: thread owns A row (merged col) = t&255, channel-half t>>8
    const int  srow = t & 255, shalf = t >> 8;
    const int  si = srow >> 6, sw = srow & 63;
    const bool valid = (sw < 56);
    char* xs_base = smem + srow * 112 + shalf * 16;   // + buf + tap*32

    for (int slab = blockIdx.x; slab < NSLABS; slab += NCTA) {
        const int h = slab % 19, b = slab / 19;
        const int y0 = 3 * h - 1;

        float d[4][2][4];
        #pragma unroll
        for (int jm = 0; jm < 4; jm++)
            #pragma unroll
            for (int jn = 0; jn < 2; jn++)
                #pragma unroll
                for (int q = 0; q < 4; q++) d[jm][jn][q] = 0.f;

        for (int chunk = 0; chunk < 4; chunk++) {
            const int buf = chunk & 1;

            // ---- stage X chunk: per tap, 8 channel planes -> one STS.128
            {
                const float* xb = x + ((size_t)(b * 256 + si * 64 +
                                    chunk * 16 + shalf * 8) * 56) * 56 + sw;
                char* xdst = xs_base + buf * 28672;
                #pragma unroll
                for (int tap = 0; tap < 3; tap++) {
                    const int y = y0 + tap;
                    float v[8];
                    if (valid && y >= 0) {
                        #pragma unroll
                        for (int j = 0; j < 8; j++) v[j] = xb[j * 3136 + y * 56];
                    } else {
                        #pragma unroll
                        for (int j = 0; j < 8; j++) v[j] = 0.f;
                    }
                    uint4 p;
                    p.x = pkh2(v[0], v[1]); p.y = pkh2(v[2], v[3]);
                    p.z = pkh2(v[4], v[5]); p.w = pkh2(v[6], v[7]);
                    *(uint4*)(xdst + tap * 32) = p;
                }
            }
            __syncthreads();

            // ---- MMA over chunk: 3 k16-steps (ks == tap in permuted K)
            #pragma unroll
            for (int ks = 0; ks < 3; ks++) {
                uint32_t bfr[4];
                ldmx4(bfr, b_base + chunk * 96 + ks * 32);
                #pragma unroll
                for (int jm = 0; jm < 4; jm++) {
                    uint32_t afr[4];
                    ldmx4(afr, a_base + buf * 28672 + jm * 1792 + ks * 32);
                    mma_fp16(d[jm][0], afr, bfr[0], bfr[1]);
                    mma_fp16(d[jm][1], afr, bfr[2], bfr[3]);
                }
            }
        }
        __syncthreads();   // all MMAs done; feat overlays X buffers

        // ---- dump D -> feat[n][m]
        #pragma unroll
        for (int jm = 0; jm < 4; jm++)
            #pragma unroll
            for (int jn = 0; jn < 2; jn++) {
                const int m0 = wm * 64 + 16 * jm + r;
                const int n0 = wn * 16 + 8 * jn + 2 * cq;
                feat[n0 * FT_S + m0]           = d[jm][jn][0];
                feat[(n0 + 1) * FT_S + m0]     = d[jm][jn][1];
                feat[n0 * FT_S + m0 + 8]       = d[jm][jn][2];
                feat[(n0 + 1) * FT_S + m0 + 8] = d[jm][jn][3];
            }
        __syncthreads();

        // ---- vectorized epilogue: group g = o*14 + (w0/4); 7 iters/thread.
        //      out[b,o,h,1+w0..1+w0+3] = sum_i cf4[o][i]*feat4[ofs4[o][i] + w0]
        {
            float* ob = out + ((size_t)(b * 256) * 19 + h) * 58;
            #pragma unroll
            for (int j = 0; j < 7; j++) {
                const int g  = j * 512 + t;
                const int o  = g / 14;
                const int w0 = (g - o * 14) * 4;
                const int4   id = *(const int4*)  (ofs_s + o * 4);
                const float4 cf = *(const float4*)(cf_s  + o * 4);
                float4 f0 = *(const float4*)(feat + id.x + w0);
                float4 f1 = *(const float4*)(feat + id.y + w0);
                float4 f2 = *(const float4*)(feat + id.z + w0);
                float4 f3 = *(const float4*)(feat + id.w + w0);
                float r0 = cf.x*f0.x + cf.y*f1.x + cf.z*f2.x + cf.w*f3.x;
                float r1 = cf.x*f0.y + cf.y*f1.y + cf.z*f2.y + cf.w*f3.y;
                float r2 = cf.x*f0.z + cf.y*f1.z + cf.z*f2.z + cf.w*f3.z;
                float r3 = cf.x*f0.w + cf.y*f1.w + cf.z*f2.w + cf.w*f3.w;
                float* op = ob + o * 1102 + w0 + 1;
                op[0] = r0; op[1] = r1; op[2] = r2; op[3] = r3;
            }
            // exact-zero borders w=0, w=57
            const int oo = t >> 1, ww = (t & 1) ? 57 : 0;
            ob[oo * 1102 + ww] = 0.f;
        }
        __syncthreads();   // feat fully read before next slab's STS
    }
}

extern "C" void kernel_launch(void* const* d_in, const int* in_sizes, int n_in,
                              void* d_out, int out_size) {
    const float* x     = (const float*)d_in[0];   // 32*256*56*56
    const float* lego  = (const float*)d_in[1];   // 64*64*3*1
    const float* coefs = (const float*)d_in[2];   // 4*256*64
    const float* comb  = (const float*)d_in[3];   // 4*256*64
    float* out = (float*)d_out;                   // 32*256*19*58
    (void)in_sizes; (void)n_in; (void)out_size;

    cudaFuncSetAttribute(main_kernel,
                         cudaFuncAttributeMaxDynamicSharedMemorySize, SM_SZ);
    main_kernel<<<NCTA, 512, SM_SZ>>>(x, lego, coefs, comb, out);
}

// round 15
// speedup vs baseline: 1.0872x; 1.0872x over previous
#include <cuda_runtime.h>
#include <cuda_fp16.h>
#include <stdint.h>

// LegoConv2d GB300 — R14: R12 (94us) + cp.async staging pipeline.
// fp16 1-term mma.sync GEMM per slab (b,h): feat[256 x 64] = X^T @ lego,
// fp32 accum, permuted K (k = chunk*48 + tap*16 + c16), 2 CTAs/SM.
// NEW: x staged as raw fp32 via cp.async in 24-k sub-chunks (2 deep,
// zfill for padding), converted to fp16 from smem (no LDG stall exposure).
// MMA / dump / epilogue identical to the proven R12 kernel.

#define NCTA   304
#define NSLABS 608
#define FT_S   260            // feat row stride (f32), conflict-free dump

// smem byte offsets (per CTA, 111616 B -> 2 CTAs/SM)
#define SM_F32 0              // two F32 sub bufs: 256 rows x 96B = 24576 each
#define SM_H16 49152          // fp16 chunk buf: 256 rows x 112B = 28672
#define SM_LG  77824          // lego: 64 n x 400B = 25600
#define SM_ID  103424         // int[1024]
#define SM_CF  107520         // float[1024]
#define SM_SZ  111616
// feat (f32 64 x FT_S = 66560 B) overlays F32 bufs + head of H16

__device__ __forceinline__ uint32_t smem_u32(const void* p) {
    uint32_t a;
    asm("{ .reg .u64 t; cvta.to.shared.u64 t, %1; cvt.u32.u64 %0, t; }" : "=r"(a) : "l"(p));
    return a;
}
__device__ __forceinline__ void cp4(uint32_t dst, const float* src, uint32_t sz) {
    asm volatile("cp.async.ca.shared.global [%0], [%1], 4, %2;"
                 :: "r"(dst), "l"(src), "r"(sz) : "memory");
}
__device__ __forceinline__ void cp_commit() {
    asm volatile("cp.async.commit_group;" ::: "memory");
}
__device__ __forceinline__ void cp_wait1() {
    asm volatile("cp.async.wait_group 1;" ::: "memory");
}
__device__ __forceinline__ void ldmx4(uint32_t* r, uint32_t addr) {
    asm volatile("ldmatrix.sync.aligned.m8n8.x4.shared.b16 {%0,%1,%2,%3}, [%4];"
                 : "=r"(r[0]), "=r"(r[1]), "=r"(r[2]), "=r"(r[3]) : "r"(addr));
}
__device__ __forceinline__ void mma_fp16(float* d, const uint32_t* a,
                                         uint32_t b0, uint32_t b1) {
    asm volatile(
        "mma.sync.aligned.m16n8k16.row.col.f32.f16.f16.f32 "
        "{%0,%1,%2,%3}, {%4,%5,%6,%7}, {%8,%9}, {%0,%1,%2,%3};"
        : "+f"(d[0]), "+f"(d[1]), "+f"(d[2]), "+f"(d[3])
        : "r"(a[0]), "r"(a[1]), "r"(a[2]), "r"(a[3]), "r"(b0), "r"(b1));
}
__device__ __forceinline__ uint32_t pkh2(float lo, float hi) {
    __half2 h = __floats2half2_rn(lo, hi);
    return *(uint32_t*)&h;
}

extern __shared__ char smem[];

__global__ __launch_bounds__(512, 2)
void main_kernel(const float* __restrict__ x,
                 const float* __restrict__ lego,
                 const float* __restrict__ coefs,
                 const float* __restrict__ comb,
                 float* __restrict__ out)
{
    const int t = threadIdx.x, lane = t & 31, wid = t >> 5;
    const uint32_t sb = smem_u32(smem);

    int*   idx_s  = (int*)(smem + SM_ID);
    float* coef_s = (float*)(smem + SM_CF);

    // ---- fused prep: warp-parallel first-max argmax + coefficient pick
    for (int row = wid * 64; row < wid * 64 + 64; row++) {
        float v = comb[(size_t)row * 64 + lane];
        int   i = lane;
        {
            float v2 = comb[(size_t)row * 64 + 32 + lane];
            if (v2 > v) { v = v2; i = lane + 32; }
        }
        #pragma unroll
        for (int off = 16; off; off >>= 1) {
            float ov = __shfl_xor_sync(0xFFFFFFFFu, v, off);
            int   oi = __shfl_xor_sync(0xFFFFFFFFu, i, off);
            if (ov > v || (ov == v && oi < i)) { v = ov; i = oi; }
        }
        if (lane == 0) {
            idx_s[row]  = i;
            coef_s[row] = coefs[(size_t)row * 64 + i];
        }
    }

    // ---- stage lego fp16 once, K-permuted: k = (c>>4)*48 + tap*16 + (c&15)
    {
        __half* lg = (__half*)(smem + SM_LG);
        for (int s = t; s < 64 * 192; s += 512) {
            int n = s / 192, r = s - n * 192, c = r / 3, tap = r - c * 3;
            int k = (c >> 4) * 48 + tap * 16 + (c & 15);
            lg[n * 200 + k] = __float2half_rn(lego[s]);
        }
    }
    __syncthreads();

    const int wm = wid & 3, wn = wid >> 2;      // warp grid 4(M) x 4(N)
    const int r  = lane >> 2, cq = lane & 3;

    // ldmatrix lane base addresses (A stride 112B, B stride 400B — proven)
    const uint32_t a_base = sb + SM_H16 +
        (uint32_t)((wm * 64 + (lane & 15)) * 112 + (lane >> 4) * 16);
    const uint32_t b_base = sb + SM_LG +
        (uint32_t)((wn * 16 + 8 * ((lane >> 4) & 1) + (lane & 7)) * 400 +
                   16 * ((lane >> 3) & 1));

    float* feat = (float*)smem;

    // staging role: thread owns A row (merged col) = t&255, channel-quad t>>8
    const int  srow = t & 255, shalf = t >> 8;  // shalf in {0,1}
    const int  si = srow >> 6, sw = srow & 63;
    const bool valid = (sw < 56);
    // F32 smem base for this thread (per sub: + (s&1)*24576 + tap*32 + q*4)
    const uint32_t f32t = sb + (uint32_t)(srow * 96 + shalf * 16);
    // H16 dst base (per sub: + tap*32 + (s&1)*16)
    char* h16t = smem + SM_H16 + srow * 112 + shalf * 8;

    for (int slab = blockIdx.x; slab < NSLABS; slab += NCTA) {
        const int h = slab % 19, b = slab / 19;
        const int y0 = 3 * h - 1;
        const float* xslab = x + ((size_t)(b * 256 + si * 64) * 56) * 56 + sw;
        // clamped tap rows + zfill sizes
        int      yc[3];
        uint32_t sz[3];
        #pragma unroll
        for (int tap = 0; tap < 3; tap++) {
            const int y = y0 + tap;
            yc[tap] = (y < 0) ? 0 : y;
            sz[tap] = (valid && y >= 0) ? 4u : 0u;
        }

        float d[4][2][4];
        #pragma unroll
        for (int jm = 0; jm < 4; jm++)
            #pragma unroll
            for (int jn = 0; jn < 2; jn++)
                #pragma unroll
                for (int q = 0; q < 4; q++) d[jm][jn][q] = 0.f;

        // ---- prologue: cp.async subs 0,1  (sub s: channels s*8+shalf*4..+3)
        #pragma unroll
        for (int s = 0; s < 2; s++) {
            const float* xg = xslab + (size_t)(s * 8 + shalf * 4) * 3136;
            const uint32_t fd = f32t + s * 24576;
            #pragma unroll
            for (int tap = 0; tap < 3; tap++)
                #pragma unroll
                for (int q = 0; q < 4; q++)
                    cp4(fd + tap * 32 + q * 4, xg + q * 3136 + yc[tap] * 56, sz[tap]);
            cp_commit();
        }

        for (int mc = 0; mc < 4; mc++) {
            // ---- two sub-chunks: wait -> convert own data -> prefetch s+2
            #pragma unroll
            for (int sh = 0; sh < 2; sh++) {
                const int s = 2 * mc + sh;
                cp_wait1();                       // sub s landed (own data only)
                // convert: 3x LDS.128 -> 12 cvt -> 3x STS.64
                const float* fsrc = (const float*)(smem + (s & 1) * 24576 +
                                                   srow * 96 + shalf * 16);
                char* hdst = h16t + (s & 1) * 16;
                #pragma unroll
                for (int tap = 0; tap < 3; tap++) {
                    float4 v = *(const float4*)(fsrc + tap * 8);
                    uint2 p;
                    p.x = pkh2(v.x, v.y);
                    p.y = pkh2(v.z, v.w);
                    *(uint2*)(hdst + tap * 32) = p;
                }
                // prefetch sub s+2 into the buffer just drained
                if (s + 2 < 8) {
                    const float* xg = xslab +
                        (size_t)((s + 2) * 8 + shalf * 4) * 3136;
                    const uint32_t fd = f32t + (s & 1) * 24576;
                    #pragma unroll
                    for (int tap = 0; tap < 3; tap++)
                        #pragma unroll
                        for (int q = 0; q < 4; q++)
                            cp4(fd + tap * 32 + q * 4,
                                xg + q * 3136 + yc[tap] * 56, sz[tap]);
                }
                cp_commit();                      // empty group at tail is fine
            }
            __syncthreads();                      // H16 chunk complete

            // ---- MMA over chunk mc: 3 k16-steps (ks == tap in permuted K)
            #pragma unroll
            for (int ks = 0; ks < 3; ks++) {
                uint32_t bfr[4];
                ldmx4(bfr, b_base + mc * 96 + ks * 32);
                #pragma unroll
                for (int jm = 0; jm < 4; jm++) {
                    uint32_t afr[4];
                    ldmx4(afr, a_base + jm * 1792 + ks * 32);
                    mma_fp16(d[jm][0], afr, bfr[0], bfr[1]);
                    mma_fp16(d[jm][1], afr, bfr[2], bfr[3]);
                }
            }
            __syncthreads();                      // H16 reads done before refill
        }

        // ---- dump D -> feat[n][m]  (feat overlays F32/H16 head)
        #pragma unroll
        for (int jm = 0; jm < 4; jm++)
            #pragma unroll
            for (int jn = 0; jn < 2; jn++) {
                const int m0 = wm * 64 + 16 * jm + r;
                const int n0 = wn * 16 + 8 * jn + 2 * cq;
                feat[n0 * FT_S + m0]           = d[jm][jn][0];
                feat[(n0 + 1) * FT_S + m0]     = d[jm][jn][1];
                feat[n0 * FT_S + m0 + 8]       = d[jm][jn][2];
                feat[(n0 + 1) * FT_S + m0 + 8] = d[jm][jn][3];
            }
        __syncthreads();

        // ---- epilogue (R12-proven): out[b,o,h,w+1] = sum_i cf*feat[idx][i*64+w]
        {
            float* ob = out + ((size_t)(b * 256) * 19 + h) * 58;
            int o = t / 56, w = t - o * 56;
            #pragma unroll 4
            for (int it = 0; it < 28; it++) {
                float acc = 0.f;
                #pragma unroll
                for (int i = 0; i < 4; i++) {
                    const int   id = idx_s[i * 256 + o];
                    const float cf = coef_s[i * 256 + o];
                    acc = fmaf(cf, feat[id * FT_S + i * 64 + w], acc);
                }
                ob[o * 1102 + w + 1] = acc;
                o += 9; w += 8;
                if (w >= 56) { w -= 56; o += 1; }
            }
            // exact-zero borders w=0, w=57
            const int oo = t >> 1, ww = (t & 1) ? 57 : 0;
            ob[oo * 1102 + ww] = 0.f;
        }
        __syncthreads();   // feat fully read before next slab's cp.async/STS
    }
}

extern "C" void kernel_launch(void* const* d_in, const int* in_sizes, int n_in,
                              void* d_out, int out_size) {
    const float* x     = (const float*)d_in[0];   // 32*256*56*56
    const float* lego  = (const float*)d_in[1];   // 64*64*3*1
    const float* coefs = (const float*)d_in[2];   // 4*256*64
    const float* comb  = (const float*)d_in[3];   // 4*256*64
    float* out = (float*)d_out;                   // 32*256*19*58
    (void)in_sizes; (void)n_in; (void)out_size;

    cudaFuncSetAttribute(main_kernel,
                         cudaFuncAttributeMaxDynamicSharedMemorySize, SM_SZ);
    main_kernel<<<NCTA, 512, SM_SZ>>>(x, lego, coefs, comb, out);
}